// round 11
// baseline (speedup 1.0000x reference)
#include <cuda_runtime.h>
#include <cuda_bf16.h>
#include <cstdint>

// Problem constants
#define B_ 4
#define S_ 2048
#define D_ 1024
#define H_ 16
#define DH_ 64
#define N3D 3072           // 3*D
#define M_ (B_ * S_)       // 8192 rows

// ---------------------------------------------------------------------------
// Device scratch (allocation-free rule)
// ---------------------------------------------------------------------------
__device__ __align__(256) __nv_bfloat16 g_xhi[M_ * D_];
__device__ __align__(256) __nv_bfloat16 g_xlo[M_ * D_];
__device__ __align__(256) __nv_bfloat16 g_wthi[N3D * D_];   // W_qkv^T [n][k]
__device__ __align__(256) __nv_bfloat16 g_wtlo[N3D * D_];
__device__ __align__(256) __nv_bfloat16 g_wothi[D_ * D_];   // W_out^T [n][k]
__device__ __align__(256) __nv_bfloat16 g_wotlo[D_ * D_];
__device__ __align__(256) float g_q[B_ * H_ * S_ * DH_];    // fp32 head-major
__device__ __align__(256) float g_k[B_ * H_ * S_ * DH_];
__device__ __align__(256) float g_v[B_ * H_ * S_ * DH_];
__device__ __align__(256) __nv_bfloat16 g_ctxhi[M_ * D_];   // [b*S+s][d]
__device__ __align__(256) __nv_bfloat16 g_ctxlo[M_ * D_];

// ---------------------------------------------------------------------------
// PTX helpers (sm_80+ standard instructions only — no tcgen05: harness PTX
// target is plain sm_103, 'a'-suffix features are unavailable)
// ---------------------------------------------------------------------------
__device__ __forceinline__ uint32_t smem_to_u32(const void* p) {
  uint32_t a;
  asm("{ .reg .u64 t; cvta.to.shared.u64 t, %1; cvt.u32.u64 %0, t; }"
      : "=r"(a) : "l"(p));
  return a;
}

#define CP_ASYNC16(dst, src)                                              \
  asm volatile("cp.async.cg.shared.global [%0], [%1], 16;" ::"r"(dst),    \
               "l"(src) : "memory")
#define CP_COMMIT() asm volatile("cp.async.commit_group;" ::: "memory")
#define CP_WAIT1() asm volatile("cp.async.wait_group 1;" ::: "memory")
#define CP_WAIT0() asm volatile("cp.async.wait_group 0;" ::: "memory")

#define LDSM4(r, addr)                                                     \
  asm volatile(                                                            \
      "ldmatrix.sync.aligned.m8n8.x4.shared.b16 {%0,%1,%2,%3}, [%4];"      \
      : "=r"((r)[0]), "=r"((r)[1]), "=r"((r)[2]), "=r"((r)[3])             \
      : "r"(addr))

#define MMA16816(c, a, b0, b1)                                              \
  asm volatile(                                                             \
      "mma.sync.aligned.m16n8k16.row.col.f32.bf16.bf16.f32 "                \
      "{%0,%1,%2,%3}, {%4,%5,%6,%7}, {%8,%9}, {%0,%1,%2,%3};"               \
      : "+f"((c)[0]), "+f"((c)[1]), "+f"((c)[2]), "+f"((c)[3])              \
      : "r"((a)[0]), "r"((a)[1]), "r"((a)[2]), "r"((a)[3]), "r"(b0),        \
        "r"(b1))

// ---------------------------------------------------------------------------
// Converter: fp32 -> bf16 hi/lo split (element-wise, vectorized by 4)
// ---------------------------------------------------------------------------
__global__ void convert_split(const float* __restrict__ X, int n4,
                              __nv_bfloat16* __restrict__ hi,
                              __nv_bfloat16* __restrict__ lo) {
  int i = blockIdx.x * blockDim.x + threadIdx.x;
  if (i >= n4) return;
  float4 v = ((const float4*)X)[i];
  __nv_bfloat162 ha, hb, la, lb;
  ha.x = __float2bfloat16(v.x);
  ha.y = __float2bfloat16(v.y);
  hb.x = __float2bfloat16(v.z);
  hb.y = __float2bfloat16(v.w);
  la.x = __float2bfloat16(v.x - __bfloat162float(ha.x));
  la.y = __float2bfloat16(v.y - __bfloat162float(ha.y));
  lb.x = __float2bfloat16(v.z - __bfloat162float(hb.x));
  lb.y = __float2bfloat16(v.w - __bfloat162float(hb.y));
  ((__nv_bfloat162*)hi)[2 * i] = ha;
  ((__nv_bfloat162*)hi)[2 * i + 1] = hb;
  ((__nv_bfloat162*)lo)[2 * i] = la;
  ((__nv_bfloat162*)lo)[2 * i + 1] = lb;
}

// ---------------------------------------------------------------------------
// Converter: transpose W[K][N] -> WT[N][K] with bf16 hi/lo split
// ---------------------------------------------------------------------------
__global__ void transpose_convert(const float* __restrict__ W, int Kd, int Nd,
                                  __nv_bfloat16* __restrict__ WT_hi,
                                  __nv_bfloat16* __restrict__ WT_lo) {
  __shared__ float t[32][33];
  int n0 = blockIdx.x * 32, k0 = blockIdx.y * 32;
  int tx = threadIdx.x;
  for (int r = threadIdx.y; r < 32; r += 8)
    t[r][tx] = W[(size_t)(k0 + r) * Nd + n0 + tx];
  __syncthreads();
  for (int r = threadIdx.y; r < 32; r += 8) {
    float v = t[tx][r];  // = W[k0+tx][n0+r]
    __nv_bfloat16 h = __float2bfloat16(v);
    size_t o = (size_t)(n0 + r) * Kd + k0 + tx;
    WT_hi[o] = h;
    WT_lo[o] = __float2bfloat16(v - __bfloat162float(h));
  }
}

// ---------------------------------------------------------------------------
// bf16x3 GEMM via mma.sync: C[M,N] = A[M,K] @ B^T[N,K] + bias
//   A,B in K-major bf16 hi/lo. 128x128 CTA tile, BK=64, double-buffered
//   cp.async. 8 warps, 64x32 warp tiles, m16n8k16 fragments via ldmatrix.
//   Row pad: 72 bf16 (144 B) -> conflict-free ldmatrix (bank phase 4 per row).
//   mode 0: scatter into head-major g_q/g_k/g_v ; mode 1: row-major out.
// ---------------------------------------------------------------------------
#define TILE_B 18432            // 128 rows * 144 B
#define STAGE_B (4 * TILE_B)    // Ah, Al, Bh, Bl
#define GEMM_SMEM (2 * STAGE_B) // 147456 B

__device__ __forceinline__ void stage_copy(uint32_t sb,
                                           const __nv_bfloat16* gAh,
                                           const __nv_bfloat16* gAl,
                                           const __nv_bfloat16* gBh,
                                           const __nv_bfloat16* gBl,
                                           int Kdim, int kc16, int tid) {
  const __nv_bfloat16* gp[4] = {gAh, gAl, gBh, gBl};
#pragma unroll
  for (int t4 = 0; t4 < 4; ++t4) {
    uint32_t tb = sb + t4 * TILE_B;
    const char* gb = (const char*)gp[t4];
#pragma unroll
    for (int i = 0; i < 4; ++i) {
      int id = tid + 256 * i;          // 1024 chunks: 128 rows x 8 x 16B
      int row = id >> 3, c = id & 7;
      uint32_t dst = tb + row * 144 + c * 16;
      const char* src = gb + ((size_t)row * Kdim + (size_t)(kc16 + c) * 8) * 2;
      CP_ASYNC16(dst, src);
    }
  }
}

__global__ __launch_bounds__(256, 1) void mma_gemm(
    const __nv_bfloat16* __restrict__ Ah, const __nv_bfloat16* __restrict__ Al,
    const __nv_bfloat16* __restrict__ Bh, const __nv_bfloat16* __restrict__ Bl,
    const float* __restrict__ bias, int Kdim, int mode,
    float* __restrict__ outp, float* __restrict__ qp, float* __restrict__ kp,
    float* __restrict__ vp) {
  extern __shared__ __align__(1024) char smem[];
  const uint32_t sm0 = smem_to_u32(smem);
  const int tid = threadIdx.x;
  const int lane = tid & 31;
  const int wid = tid >> 5;
  const int bn0 = blockIdx.x * 128;
  const int bm0 = blockIdx.y * 128;
  const int wm = (wid >> 2) * 64;   // warp m offset in CTA tile
  const int wn = (wid & 3) * 32;    // warp n offset

  const __nv_bfloat16* gAh = Ah + (size_t)bm0 * Kdim;
  const __nv_bfloat16* gAl = Al + (size_t)bm0 * Kdim;
  const __nv_bfloat16* gBh = Bh + (size_t)bn0 * Kdim;
  const __nv_bfloat16* gBl = Bl + (size_t)bn0 * Kdim;

  float acc[4][4][4];
#pragma unroll
  for (int f = 0; f < 4; ++f)
#pragma unroll
    for (int j = 0; j < 4; ++j)
#pragma unroll
      for (int r = 0; r < 4; ++r) acc[f][j][r] = 0.f;

  const int nkt = Kdim >> 6;  // K tiles of 64
  stage_copy(sm0, gAh, gAl, gBh, gBl, Kdim, 0, tid);
  CP_COMMIT();
  stage_copy(sm0 + STAGE_B, gAh, gAl, gBh, gBl, Kdim, 8, tid);
  CP_COMMIT();

  const uint32_t lrow = lane & 15;
  const uint32_t lsel = (lane >> 4) * 16;

  for (int kt = 0; kt < nkt; ++kt) {
    if (kt == nkt - 1) CP_WAIT0(); else CP_WAIT1();
    __syncthreads();
    const uint32_t sb = sm0 + (kt & 1) * STAGE_B;
    const uint32_t aBaseH = sb + (wm + lrow) * 144 + lsel;
    const uint32_t aBaseL = aBaseH + TILE_B;
    const uint32_t bBaseH = sb + 2 * TILE_B + (wn + lrow) * 144 + lsel;
    const uint32_t bBaseL = bBaseH + TILE_B;

#pragma unroll
    for (int s = 0; s < 4; ++s) {
      const uint32_t ko = s * 32;
      uint32_t ah[4][4], al[4][4], bh[2][4], bl[2][4];
#pragma unroll
      for (int f = 0; f < 4; ++f) {
        LDSM4(ah[f], aBaseH + f * (16 * 144) + ko);
        LDSM4(al[f], aBaseL + f * (16 * 144) + ko);
      }
#pragma unroll
      for (int g = 0; g < 2; ++g) {
        LDSM4(bh[g], bBaseH + g * (16 * 144) + ko);
        LDSM4(bl[g], bBaseL + g * (16 * 144) + ko);
      }
#pragma unroll
      for (int f = 0; f < 4; ++f) {
#pragma unroll
        for (int j = 0; j < 4; ++j) {
          const int g = j >> 1, hb = j & 1;
          MMA16816(acc[f][j], ah[f], bh[g][hb], bh[g][hb + 2]);
          MMA16816(acc[f][j], ah[f], bl[g][hb], bl[g][hb + 2]);
          MMA16816(acc[f][j], al[f], bh[g][hb], bh[g][hb + 2]);
        }
      }
    }
    __syncthreads();
    if (kt + 2 < nkt) {
      stage_copy(sb, gAh, gAl, gBh, gBl, Kdim, (kt + 2) * 8, tid);
      CP_COMMIT();
    }
  }

  // Epilogue: c0c1 at (row, col..col+1), c2c3 at (row+8, col..col+1)
  const int rbase = bm0 + wm + (lane >> 2);
  const int cbase = bn0 + wn + (lane & 3) * 2;
#pragma unroll
  for (int f = 0; f < 4; ++f) {
#pragma unroll
    for (int j = 0; j < 4; ++j) {
      const int col = cbase + j * 8;
      const float bx = __ldg(&bias[col]);
      const float by = __ldg(&bias[col + 1]);
      const int m0 = rbase + f * 16;
      if (mode == 0) {
        const int which = col >> 10;
        const int h = (col >> 6) & 15;
        const int dh = col & 63;
        float* dst = (which == 0) ? qp : (which == 1) ? kp : vp;
#pragma unroll
        for (int half = 0; half < 2; ++half) {
          const int m = m0 + half * 8;
          const int b = m >> 11, s = m & 2047;
          float2 v2 = make_float2(acc[f][j][half * 2] + bx,
                                  acc[f][j][half * 2 + 1] + by);
          *(float2*)&dst[(size_t)(((b << 4) + h) * 2048 + s) * 64 + dh] = v2;
        }
      } else {
#pragma unroll
        for (int half = 0; half < 2; ++half) {
          const int m = m0 + half * 8;
          float2 v2 = make_float2(acc[f][j][half * 2] + bx,
                                  acc[f][j][half * 2 + 1] + by);
          *(float2*)&outp[(size_t)m * 1024 + col] = v2;
        }
      }
    }
  }
}

// ---------------------------------------------------------------------------
// Fused attention (flash-style), fp32, online softmax. Epilogue writes ctx
// as bf16 hi/lo for the tensor-core out-projection.
// ---------------------------------------------------------------------------
#define SKV 68
#define ATTN_SMEM (4 * 64 * SKV * 4)

__global__ __launch_bounds__(256, 2) void attn_kernel(const int* __restrict__ mask) {
  extern __shared__ float sm[];
  float* Qs = sm;
  float* Ks = sm + 64 * SKV;
  float* Vs = sm + 2 * 64 * SKV;
  float* Ps = sm + 3 * 64 * SKV;

  const int qb = blockIdx.x;
  const int bh = blockIdx.y;
  const int b = bh >> 4;
  const int h = bh & 15;
  const int qm0 = qb * 64;

  const float* Qg = g_q + bh * (S_ * DH_) + qm0 * DH_;
  const float* Kg = g_k + bh * (S_ * DH_);
  const float* Vg = g_v + bh * (S_ * DH_);
  const int* Mg = mask + b * (S_ * S_) + qm0 * S_;

  const int tid = threadIdx.x;
  const int ty = tid >> 4;
  const int tx = tid & 15;
  const int r0 = ty * 4;
  const int cPV = tx * 4;

#pragma unroll
  for (int i = 0; i < 4; ++i) {
    int idx4 = tid + 256 * i;
    int row = idx4 >> 4;
    int col = (idx4 & 15) * 4;
    *(float4*)&Qs[row * SKV + col] = *(const float4*)&Qg[row * 64 + col];
  }

  float O[4][4];
  float mi[4], li[4];
#pragma unroll
  for (int i = 0; i < 4; ++i) {
    mi[i] = -1e30f;
    li[i] = 0.f;
#pragma unroll
    for (int j = 0; j < 4; ++j) O[i][j] = 0.f;
  }

  for (int kn0 = 0; kn0 < S_; kn0 += 64) {
#pragma unroll
    for (int i = 0; i < 4; ++i) {
      int idx4 = tid + 256 * i;
      int row = idx4 >> 4;
      int col = (idx4 & 15) * 4;
      *(float4*)&Ks[row * SKV + col] =
          *(const float4*)&Kg[(kn0 + row) * 64 + col];
      *(float4*)&Vs[row * SKV + col] =
          *(const float4*)&Vg[(kn0 + row) * 64 + col];
    }
    __syncthreads();

    float s[4][4];
#pragma unroll
    for (int i = 0; i < 4; ++i)
#pragma unroll
      for (int j = 0; j < 4; ++j) s[i][j] = 0.f;

#pragma unroll
    for (int k = 0; k < 64; k += 4) {
      float4 qv[4], kv[4];
#pragma unroll
      for (int i = 0; i < 4; ++i)
        qv[i] = *(const float4*)&Qs[(r0 + i) * SKV + k];
#pragma unroll
      for (int j = 0; j < 4; ++j)
        kv[j] = *(const float4*)&Ks[(tx + 16 * j) * SKV + k];
#pragma unroll
      for (int i = 0; i < 4; ++i)
#pragma unroll
        for (int j = 0; j < 4; ++j)
          s[i][j] += qv[i].x * kv[j].x + qv[i].y * kv[j].y +
                     qv[i].z * kv[j].z + qv[i].w * kv[j].w;
    }

#pragma unroll
    for (int i = 0; i < 4; ++i) {
      int row = r0 + i;
      const int* mrow = Mg + row * S_ + kn0;
      float sv[4];
#pragma unroll
      for (int j = 0; j < 4; ++j) {
        int mv = mrow[tx + 16 * j];
        sv[j] = mv ? s[i][j] * 0.125f : -1000.0f;
      }
      float rmax = fmaxf(fmaxf(sv[0], sv[1]), fmaxf(sv[2], sv[3]));
#pragma unroll
      for (int o = 8; o > 0; o >>= 1)
        rmax = fmaxf(rmax, __shfl_xor_sync(0xffffffffu, rmax, o));
      float mnew = fmaxf(mi[i], rmax);
      float corr = __expf(mi[i] - mnew);
      mi[i] = mnew;
      float rsum = 0.f;
#pragma unroll
      for (int j = 0; j < 4; ++j) {
        float p = __expf(sv[j] - mnew);
        rsum += p;
        Ps[row * SKV + tx + 16 * j] = p;
      }
#pragma unroll
      for (int o = 8; o > 0; o >>= 1)
        rsum += __shfl_xor_sync(0xffffffffu, rsum, o);
      li[i] = li[i] * corr + rsum;
      O[i][0] *= corr; O[i][1] *= corr; O[i][2] *= corr; O[i][3] *= corr;
    }
    __syncthreads();

#pragma unroll
    for (int n = 0; n < 64; n += 4) {
      float4 pr[4], vr[4];
#pragma unroll
      for (int i = 0; i < 4; ++i)
        pr[i] = *(const float4*)&Ps[(r0 + i) * SKV + n];
#pragma unroll
      for (int j = 0; j < 4; ++j)
        vr[j] = *(const float4*)&Vs[(n + j) * SKV + cPV];
#pragma unroll
      for (int i = 0; i < 4; ++i) {
        O[i][0] += pr[i].x * vr[0].x + pr[i].y * vr[1].x +
                   pr[i].z * vr[2].x + pr[i].w * vr[3].x;
        O[i][1] += pr[i].x * vr[0].y + pr[i].y * vr[1].y +
                   pr[i].z * vr[2].y + pr[i].w * vr[3].y;
        O[i][2] += pr[i].x * vr[0].z + pr[i].y * vr[1].z +
                   pr[i].z * vr[2].z + pr[i].w * vr[3].z;
        O[i][3] += pr[i].x * vr[0].w + pr[i].y * vr[1].w +
                   pr[i].z * vr[2].w + pr[i].w * vr[3].w;
      }
    }
    __syncthreads();
  }

  // normalize + write ctx (bf16 hi/lo) in [B,S,D] layout
#pragma unroll
  for (int i = 0; i < 4; ++i) {
    float inv = 1.0f / li[i];
    int q = qm0 + r0 + i;
    float vx = O[i][0] * inv, vy = O[i][1] * inv;
    float vz = O[i][2] * inv, vw = O[i][3] * inv;
    size_t base = (size_t)(b * S_ + q) * D_ + h * 64 + cPV;
    __nv_bfloat162 h01, h23, l01, l23;
    h01.x = __float2bfloat16(vx);
    h01.y = __float2bfloat16(vy);
    h23.x = __float2bfloat16(vz);
    h23.y = __float2bfloat16(vw);
    l01.x = __float2bfloat16(vx - __bfloat162float(h01.x));
    l01.y = __float2bfloat16(vy - __bfloat162float(h01.y));
    l23.x = __float2bfloat16(vz - __bfloat162float(h23.x));
    l23.y = __float2bfloat16(vw - __bfloat162float(h23.y));
    *(__nv_bfloat162*)&g_ctxhi[base] = h01;
    *(__nv_bfloat162*)&g_ctxhi[base + 2] = h23;
    *(__nv_bfloat162*)&g_ctxlo[base] = l01;
    *(__nv_bfloat162*)&g_ctxlo[base + 2] = l23;
  }
}

// ---------------------------------------------------------------------------
extern "C" void kernel_launch(void* const* d_in, const int* in_sizes, int n_in,
                              void* d_out, int out_size) {
  const float* x     = (const float*)d_in[0];
  const int*   mask  = (const int*)d_in[1];
  const float* w_qkv = (const float*)d_in[2];
  const float* b_qkv = (const float*)d_in[3];
  const float* w_out = (const float*)d_in[4];
  const float* b_out = (const float*)d_in[5];
  float* out = (float*)d_out;

  void *pxh, *pxl, *pwth, *pwtl, *pwoh, *pwol, *pq, *pk, *pv, *pch, *pcl;
  cudaGetSymbolAddress(&pxh, g_xhi);
  cudaGetSymbolAddress(&pxl, g_xlo);
  cudaGetSymbolAddress(&pwth, g_wthi);
  cudaGetSymbolAddress(&pwtl, g_wtlo);
  cudaGetSymbolAddress(&pwoh, g_wothi);
  cudaGetSymbolAddress(&pwol, g_wotlo);
  cudaGetSymbolAddress(&pq, g_q);
  cudaGetSymbolAddress(&pk, g_k);
  cudaGetSymbolAddress(&pv, g_v);
  cudaGetSymbolAddress(&pch, g_ctxhi);
  cudaGetSymbolAddress(&pcl, g_ctxlo);

  cudaFuncSetAttribute(attn_kernel,
                       cudaFuncAttributeMaxDynamicSharedMemorySize, ATTN_SMEM);
  cudaFuncSetAttribute(mma_gemm,
                       cudaFuncAttributeMaxDynamicSharedMemorySize, GEMM_SMEM);

  // Split/convert inputs
  convert_split<<<(M_ * D_ / 4 + 255) / 256, 256>>>(
      x, M_ * D_ / 4, (__nv_bfloat16*)pxh, (__nv_bfloat16*)pxl);
  transpose_convert<<<dim3(N3D / 32, D_ / 32), dim3(32, 8)>>>(
      w_qkv, D_, N3D, (__nv_bfloat16*)pwth, (__nv_bfloat16*)pwtl);
  transpose_convert<<<dim3(D_ / 32, D_ / 32), dim3(32, 8)>>>(
      w_out, D_, D_, (__nv_bfloat16*)pwoh, (__nv_bfloat16*)pwol);

  // QKV projection (bf16x3 mma.sync), scatter to head-major q/k/v
  mma_gemm<<<dim3(N3D / 128, M_ / 128), 256, GEMM_SMEM>>>(
      (const __nv_bfloat16*)pxh, (const __nv_bfloat16*)pxl,
      (const __nv_bfloat16*)pwth, (const __nv_bfloat16*)pwtl, b_qkv, D_, 0,
      nullptr, (float*)pq, (float*)pk, (float*)pv);

  // Attention (fp32)
  attn_kernel<<<dim3(S_ / 64, B_ * H_), 256, ATTN_SMEM>>>(mask);

  // Output projection (bf16x3 mma.sync)
  mma_gemm<<<dim3(D_ / 128, M_ / 128), 256, GEMM_SMEM>>>(
      (const __nv_bfloat16*)pch, (const __nv_bfloat16*)pcl,
      (const __nv_bfloat16*)pwoh, (const __nv_bfloat16*)pwol, b_out, D_, 1,
      out, nullptr, nullptr, nullptr);
}

// round 12
// speedup vs baseline: 1.7924x; 1.7924x over previous
#include <cuda_runtime.h>
#include <cuda_bf16.h>
#include <cstdint>

// Problem constants
#define B_ 4
#define S_ 2048
#define D_ 1024
#define H_ 16
#define DH_ 64
#define N3D 3072           // 3*D
#define M_ (B_ * S_)       // 8192 rows

// ---------------------------------------------------------------------------
// Device scratch (allocation-free rule)
// ---------------------------------------------------------------------------
__device__ __align__(256) __nv_bfloat16 g_xhi[M_ * D_];
__device__ __align__(256) __nv_bfloat16 g_xlo[M_ * D_];
__device__ __align__(256) __nv_bfloat16 g_wthi[N3D * D_];   // W_qkv^T [n][k]
__device__ __align__(256) __nv_bfloat16 g_wtlo[N3D * D_];
__device__ __align__(256) __nv_bfloat16 g_wothi[D_ * D_];   // W_out^T [n][k]
__device__ __align__(256) __nv_bfloat16 g_wotlo[D_ * D_];
// head-major [bh][s][dh] bf16 hi/lo
__device__ __align__(256) __nv_bfloat16 g_qhi[B_ * H_ * S_ * DH_];
__device__ __align__(256) __nv_bfloat16 g_qlo[B_ * H_ * S_ * DH_];
__device__ __align__(256) __nv_bfloat16 g_khi[B_ * H_ * S_ * DH_];
__device__ __align__(256) __nv_bfloat16 g_klo[B_ * H_ * S_ * DH_];
__device__ __align__(256) __nv_bfloat16 g_vhi[B_ * H_ * S_ * DH_];
__device__ __align__(256) __nv_bfloat16 g_vlo[B_ * H_ * S_ * DH_];
__device__ __align__(256) __nv_bfloat16 g_ctxhi[M_ * D_];   // [b*S+s][d]
__device__ __align__(256) __nv_bfloat16 g_ctxlo[M_ * D_];

// ---------------------------------------------------------------------------
// PTX helpers (sm_80+ standard instructions only)
// ---------------------------------------------------------------------------
__device__ __forceinline__ uint32_t smem_to_u32(const void* p) {
  uint32_t a;
  asm("{ .reg .u64 t; cvta.to.shared.u64 t, %1; cvt.u32.u64 %0, t; }"
      : "=r"(a) : "l"(p));
  return a;
}

#define CP_ASYNC16(dst, src)                                              \
  asm volatile("cp.async.cg.shared.global [%0], [%1], 16;" ::"r"(dst),    \
               "l"(src) : "memory")
#define CP_COMMIT() asm volatile("cp.async.commit_group;" ::: "memory")
#define CP_WAIT1() asm volatile("cp.async.wait_group 1;" ::: "memory")
#define CP_WAIT0() asm volatile("cp.async.wait_group 0;" ::: "memory")

#define LDSM4(r, addr)                                                     \
  asm volatile(                                                            \
      "ldmatrix.sync.aligned.m8n8.x4.shared.b16 {%0,%1,%2,%3}, [%4];"      \
      : "=r"((r)[0]), "=r"((r)[1]), "=r"((r)[2]), "=r"((r)[3])             \
      : "r"(addr))

#define LDSM4T(r, addr)                                                    \
  asm volatile(                                                            \
      "ldmatrix.sync.aligned.m8n8.x4.trans.shared.b16 {%0,%1,%2,%3}, [%4];"\
      : "=r"((r)[0]), "=r"((r)[1]), "=r"((r)[2]), "=r"((r)[3])             \
      : "r"(addr))

#define MMA16816(c, a, b0, b1)                                              \
  asm volatile(                                                             \
      "mma.sync.aligned.m16n8k16.row.col.f32.bf16.bf16.f32 "                \
      "{%0,%1,%2,%3}, {%4,%5,%6,%7}, {%8,%9}, {%0,%1,%2,%3};"               \
      : "+f"((c)[0]), "+f"((c)[1]), "+f"((c)[2]), "+f"((c)[3])              \
      : "r"((a)[0]), "r"((a)[1]), "r"((a)[2]), "r"((a)[3]), "r"(b0),        \
        "r"(b1))

// FFMA-only exp (no MUFU): magic-constant round + degree-5 poly for 2^f.
// Valid for x in [-3000, 80]; rel err ~2e-6.
__device__ __forceinline__ float fexp(float x) {
  float z = fmaf(x, 1.4426950408889634f, 12582912.0f);  // n in low mantissa
  float n = z - 12582912.0f;                            // round(x*log2e)
  float f = fmaf(x, 1.4426950408889634f, -n);           // [-0.5, 0.5]
  float p = 1.33335581e-3f;
  p = fmaf(p, f, 9.61812911e-3f);
  p = fmaf(p, f, 5.55041087e-2f);
  p = fmaf(p, f, 2.40226507e-1f);
  p = fmaf(p, f, 6.93147181e-1f);
  p = fmaf(p, f, 1.0f);
  int ni = __float_as_int(z) - 0x4B400000;  // = (int)n
  ni = max(ni, -126);
  return p * __int_as_float((ni + 127) << 23);
}

// Split float pair into bf16x2 hi + bf16x2 lo (residual) regs.
__device__ __forceinline__ void split_pack(float a, float b, uint32_t& hi2,
                                           uint32_t& lo2) {
  __nv_bfloat162 hh, ll;
  hh.x = __float2bfloat16(a);
  hh.y = __float2bfloat16(b);
  ll.x = __float2bfloat16(a - __bfloat162float(hh.x));
  ll.y = __float2bfloat16(b - __bfloat162float(hh.y));
  hi2 = *(uint32_t*)&hh;
  lo2 = *(uint32_t*)&ll;
}

// ---------------------------------------------------------------------------
// Converters
// ---------------------------------------------------------------------------
__global__ void convert_split(const float* __restrict__ X, int n4,
                              __nv_bfloat16* __restrict__ hi,
                              __nv_bfloat16* __restrict__ lo) {
  int i = blockIdx.x * blockDim.x + threadIdx.x;
  if (i >= n4) return;
  float4 v = ((const float4*)X)[i];
  __nv_bfloat162 ha, hb, la, lb;
  ha.x = __float2bfloat16(v.x);
  ha.y = __float2bfloat16(v.y);
  hb.x = __float2bfloat16(v.z);
  hb.y = __float2bfloat16(v.w);
  la.x = __float2bfloat16(v.x - __bfloat162float(ha.x));
  la.y = __float2bfloat16(v.y - __bfloat162float(ha.y));
  lb.x = __float2bfloat16(v.z - __bfloat162float(hb.x));
  lb.y = __float2bfloat16(v.w - __bfloat162float(hb.y));
  ((__nv_bfloat162*)hi)[2 * i] = ha;
  ((__nv_bfloat162*)hi)[2 * i + 1] = hb;
  ((__nv_bfloat162*)lo)[2 * i] = la;
  ((__nv_bfloat162*)lo)[2 * i + 1] = lb;
}

__global__ void transpose_convert(const float* __restrict__ W, int Kd, int Nd,
                                  __nv_bfloat16* __restrict__ WT_hi,
                                  __nv_bfloat16* __restrict__ WT_lo) {
  __shared__ float t[32][33];
  int n0 = blockIdx.x * 32, k0 = blockIdx.y * 32;
  int tx = threadIdx.x;
  for (int r = threadIdx.y; r < 32; r += 8)
    t[r][tx] = W[(size_t)(k0 + r) * Nd + n0 + tx];
  __syncthreads();
  for (int r = threadIdx.y; r < 32; r += 8) {
    float v = t[tx][r];  // = W[k0+tx][n0+r]
    __nv_bfloat16 h = __float2bfloat16(v);
    size_t o = (size_t)(n0 + r) * Kd + k0 + tx;
    WT_hi[o] = h;
    WT_lo[o] = __float2bfloat16(v - __bfloat162float(h));
  }
}

// ---------------------------------------------------------------------------
// bf16x3 GEMM via mma.sync: C[M,N] = A[M,K] @ B^T[N,K] + bias
//   mode 0: split-scatter into head-major bf16 hi/lo q/k/v globals
//   mode 1: row-major fp32 out
// ---------------------------------------------------------------------------
#define TILE_B 18432            // 128 rows * 144 B
#define STAGE_B (4 * TILE_B)    // Ah, Al, Bh, Bl
#define GEMM_SMEM (2 * STAGE_B) // 147456 B

__device__ __forceinline__ void stage_copy(uint32_t sb,
                                           const __nv_bfloat16* gAh,
                                           const __nv_bfloat16* gAl,
                                           const __nv_bfloat16* gBh,
                                           const __nv_bfloat16* gBl,
                                           int Kdim, int kc16, int tid) {
  const __nv_bfloat16* gp[4] = {gAh, gAl, gBh, gBl};
#pragma unroll
  for (int t4 = 0; t4 < 4; ++t4) {
    uint32_t tb = sb + t4 * TILE_B;
    const char* gb = (const char*)gp[t4];
#pragma unroll
    for (int i = 0; i < 4; ++i) {
      int id = tid + 256 * i;          // 1024 chunks: 128 rows x 8 x 16B
      int row = id >> 3, c = id & 7;
      uint32_t dst = tb + row * 144 + c * 16;
      const char* src = gb + ((size_t)row * Kdim + (size_t)(kc16 + c) * 8) * 2;
      CP_ASYNC16(dst, src);
    }
  }
}

__global__ __launch_bounds__(256, 1) void mma_gemm(
    const __nv_bfloat16* __restrict__ Ah, const __nv_bfloat16* __restrict__ Al,
    const __nv_bfloat16* __restrict__ Bh, const __nv_bfloat16* __restrict__ Bl,
    const float* __restrict__ bias, int Kdim, int mode,
    float* __restrict__ outp) {
  extern __shared__ __align__(1024) char smem[];
  const uint32_t sm0 = smem_to_u32(smem);
  const int tid = threadIdx.x;
  const int lane = tid & 31;
  const int wid = tid >> 5;
  const int bn0 = blockIdx.x * 128;
  const int bm0 = blockIdx.y * 128;
  const int wm = (wid >> 2) * 64;   // warp m offset
  const int wn = (wid & 3) * 32;    // warp n offset

  const __nv_bfloat16* gAh = Ah + (size_t)bm0 * Kdim;
  const __nv_bfloat16* gAl = Al + (size_t)bm0 * Kdim;
  const __nv_bfloat16* gBh = Bh + (size_t)bn0 * Kdim;
  const __nv_bfloat16* gBl = Bl + (size_t)bn0 * Kdim;

  float acc[4][4][4];
#pragma unroll
  for (int f = 0; f < 4; ++f)
#pragma unroll
    for (int j = 0; j < 4; ++j)
#pragma unroll
      for (int r = 0; r < 4; ++r) acc[f][j][r] = 0.f;

  const int nkt = Kdim >> 6;
  stage_copy(sm0, gAh, gAl, gBh, gBl, Kdim, 0, tid);
  CP_COMMIT();
  stage_copy(sm0 + STAGE_B, gAh, gAl, gBh, gBl, Kdim, 8, tid);
  CP_COMMIT();

  const uint32_t lrow = lane & 15;
  const uint32_t lsel = (lane >> 4) * 16;

  for (int kt = 0; kt < nkt; ++kt) {
    if (kt == nkt - 1) CP_WAIT0(); else CP_WAIT1();
    __syncthreads();
    const uint32_t sb = sm0 + (kt & 1) * STAGE_B;
    const uint32_t aBaseH = sb + (wm + lrow) * 144 + lsel;
    const uint32_t aBaseL = aBaseH + TILE_B;
    const uint32_t bBaseH = sb + 2 * TILE_B + (wn + lrow) * 144 + lsel;
    const uint32_t bBaseL = bBaseH + TILE_B;

#pragma unroll
    for (int s = 0; s < 4; ++s) {
      const uint32_t ko = s * 32;
      uint32_t ah[4][4], al[4][4], bh[2][4], bl[2][4];
#pragma unroll
      for (int f = 0; f < 4; ++f) {
        LDSM4(ah[f], aBaseH + f * (16 * 144) + ko);
        LDSM4(al[f], aBaseL + f * (16 * 144) + ko);
      }
#pragma unroll
      for (int g = 0; g < 2; ++g) {
        LDSM4(bh[g], bBaseH + g * (16 * 144) + ko);
        LDSM4(bl[g], bBaseL + g * (16 * 144) + ko);
      }
#pragma unroll
      for (int f = 0; f < 4; ++f) {
#pragma unroll
        for (int j = 0; j < 4; ++j) {
          const int g = j >> 1, hb = j & 1;
          MMA16816(acc[f][j], ah[f], bh[g][hb], bh[g][hb + 2]);
          MMA16816(acc[f][j], ah[f], bl[g][hb], bl[g][hb + 2]);
          MMA16816(acc[f][j], al[f], bh[g][hb], bh[g][hb + 2]);
        }
      }
    }
    __syncthreads();
    if (kt + 2 < nkt) {
      stage_copy(sb, gAh, gAl, gBh, gBl, Kdim, (kt + 2) * 8, tid);
      CP_COMMIT();
    }
  }

  // Epilogue
  const int rbase = bm0 + wm + (lane >> 2);
  const int cbase = bn0 + wn + (lane & 3) * 2;
#pragma unroll
  for (int f = 0; f < 4; ++f) {
#pragma unroll
    for (int j = 0; j < 4; ++j) {
      const int col = cbase + j * 8;
      const float bx = __ldg(&bias[col]);
      const float by = __ldg(&bias[col + 1]);
      const int m0 = rbase + f * 16;
      if (mode == 0) {
        const int which = col >> 10;
        const int h = (col >> 6) & 15;
        const int dh = col & 63;
        __nv_bfloat16 *dsth, *dstl;
        if (which == 0) { dsth = g_qhi; dstl = g_qlo; }
        else if (which == 1) { dsth = g_khi; dstl = g_klo; }
        else { dsth = g_vhi; dstl = g_vlo; }
#pragma unroll
        for (int half = 0; half < 2; ++half) {
          const int m = m0 + half * 8;
          const int b = m >> 11, s = m & 2047;
          float v0 = acc[f][j][half * 2] + bx;
          float v1 = acc[f][j][half * 2 + 1] + by;
          uint32_t hi2, lo2;
          split_pack(v0, v1, hi2, lo2);
          size_t o = (size_t)(((b << 4) + h) * 2048 + s) * 64 + dh;
          *(uint32_t*)&dsth[o] = hi2;
          *(uint32_t*)&dstl[o] = lo2;
        }
      } else {
#pragma unroll
        for (int half = 0; half < 2; ++half) {
          const int m = m0 + half * 8;
          float2 v2 = make_float2(acc[f][j][half * 2] + bx,
                                  acc[f][j][half * 2 + 1] + by);
          *(float2*)&outp[(size_t)m * 1024 + col] = v2;
        }
      }
    }
  }
}

// ---------------------------------------------------------------------------
// Tensor-core flash attention, bf16x3, fp32 accum, online softmax.
// Grid (S/64, B*H), 128 threads (4 warps x 16 q-rows). K/V double-buffered.
// SMEM: Qhi,Qlo | 2 x (Khi,Klo,Vhi,Vlo), each tile 64 x 72 bf16 (144 B rows)
// ---------------------------------------------------------------------------
#define ATILE 9216                 // 64*144
#define AKV (4 * ATILE)            // one K/V buffer (Khi,Klo,Vhi,Vlo)
#define ATTN_SMEM (2 * ATILE + 2 * AKV)   // 92160

__device__ __forceinline__ void kv_stage(uint32_t db, const __nv_bfloat16* Kh,
                                         const __nv_bfloat16* Kl,
                                         const __nv_bfloat16* Vh,
                                         const __nv_bfloat16* Vl, int kn0,
                                         int tid) {
  const __nv_bfloat16* src[4] = {Kh, Kl, Vh, Vl};
#pragma unroll
  for (int t = 0; t < 4; ++t) {
    const __nv_bfloat16* g = src[t] + (size_t)kn0 * 64;
    uint32_t tb = db + t * ATILE;
#pragma unroll
    for (int i = 0; i < 4; ++i) {
      int idx = tid + 128 * i;   // 512 chunks: 64 rows x 8 x 16B
      int row = idx >> 3, c = idx & 7;
      CP_ASYNC16(tb + row * 144 + c * 16, g + row * 64 + c * 8);
    }
  }
}

__global__ __launch_bounds__(128, 2) void attn_mma(const int* __restrict__ mask) {
  extern __shared__ __align__(1024) char smem[];
  const uint32_t s0 = smem_to_u32(smem);
  const int tid = threadIdx.x;
  const int lane = tid & 31;
  const int wid = tid >> 5;
  const int qb = blockIdx.x;
  const int bh = blockIdx.y;
  const int b = bh >> 4;
  const int h = bh & 15;
  const int qm0 = qb * 64;
  const int wm = wid * 16;

  const size_t hb_off = (size_t)bh * (S_ * DH_);
  const __nv_bfloat16* Qh = g_qhi + hb_off + (size_t)qm0 * DH_;
  const __nv_bfloat16* Ql = g_qlo + hb_off + (size_t)qm0 * DH_;
  const __nv_bfloat16* Kh = g_khi + hb_off;
  const __nv_bfloat16* Kl = g_klo + hb_off;
  const __nv_bfloat16* Vh = g_vhi + hb_off;
  const __nv_bfloat16* Vl = g_vlo + hb_off;

  // Load Q tile (hi/lo)
#pragma unroll
  for (int i = 0; i < 4; ++i) {
    int idx = tid + 128 * i;   // 512 chunks
    int row = idx >> 3, c = idx & 7;
    *(uint4*)(smem + row * 144 + c * 16) = *(const uint4*)(Qh + row * 64 + c * 8);
    *(uint4*)(smem + ATILE + row * 144 + c * 16) =
        *(const uint4*)(Ql + row * 64 + c * 8);
  }
  kv_stage(s0 + 2 * ATILE, Kh, Kl, Vh, Vl, 0, tid);
  CP_COMMIT();
  __syncthreads();

  // Q fragments (persist across tiles)
  uint32_t qh[4][4], ql[4][4];
  {
    uint32_t base = s0 + (wm + (lane & 15)) * 144 + ((lane >> 4) << 4);
#pragma unroll
    for (int s = 0; s < 4; ++s) {
      LDSM4(qh[s], base + s * 32);
      LDSM4(ql[s], base + ATILE + s * 32);
    }
  }

  float O[8][4];
#pragma unroll
  for (int j = 0; j < 8; ++j)
#pragma unroll
    for (int r = 0; r < 4; ++r) O[j][r] = 0.f;
  float mi[2] = {-1001.f, -1001.f};
  float li[2] = {0.f, 0.f};

  for (int kt = 0; kt < 32; ++kt) {
    if (kt + 1 < 32) {
      kv_stage(s0 + 2 * ATILE + ((kt + 1) & 1) * AKV, Kh, Kl, Vh, Vl,
               (kt + 1) * 64, tid);
      CP_COMMIT();
      CP_WAIT1();
    } else {
      CP_WAIT0();
    }
    __syncthreads();
    const uint32_t kb = s0 + 2 * ATILE + (kt & 1) * AKV;

    // scores: 64x64 per CTA (16x64 per warp)
    float sc[8][4];
#pragma unroll
    for (int j = 0; j < 8; ++j)
#pragma unroll
      for (int r = 0; r < 4; ++r) sc[j][r] = 0.f;

#pragma unroll
    for (int s = 0; s < 4; ++s) {
      uint32_t kfh[4][4], kfl[4][4];
#pragma unroll
      for (int g = 0; g < 4; ++g) {
        uint32_t a = kb + (g * 16 + (lane & 15)) * 144 + ((lane >> 4) << 4) +
                     s * 32;
        LDSM4(kfh[g], a);
        LDSM4(kfl[g], a + ATILE);
      }
#pragma unroll
      for (int g = 0; g < 4; ++g) {
#pragma unroll
        for (int hb2 = 0; hb2 < 2; ++hb2) {
          const int j = g * 2 + hb2;
          MMA16816(sc[j], qh[s], kfh[g][hb2], kfh[g][hb2 + 2]);
          MMA16816(sc[j], qh[s], kfl[g][hb2], kfl[g][hb2 + 2]);
          MMA16816(sc[j], ql[s], kfh[g][hb2], kfh[g][hb2 + 2]);
        }
      }
    }

    // softmax (mask + scale + online update)
    const int kn0 = kt * 64;
#pragma unroll
    for (int h2 = 0; h2 < 2; ++h2) {
      const int qrow = qm0 + wm + (lane >> 2) + h2 * 8;
      const int* mrow =
          mask + (size_t)b * S_ * S_ + (size_t)qrow * S_ + kn0 + (lane & 3) * 2;
      float rmax = -1e30f;
#pragma unroll
      for (int j = 0; j < 8; ++j) {
        int2 mv = __ldg((const int2*)(mrow + j * 8));
        float x0 = mv.x ? sc[j][h2 * 2] * 0.125f : -1000.f;
        float x1 = mv.y ? sc[j][h2 * 2 + 1] * 0.125f : -1000.f;
        sc[j][h2 * 2] = x0;
        sc[j][h2 * 2 + 1] = x1;
        rmax = fmaxf(rmax, fmaxf(x0, x1));
      }
      rmax = fmaxf(rmax, __shfl_xor_sync(0xffffffffu, rmax, 1));
      rmax = fmaxf(rmax, __shfl_xor_sync(0xffffffffu, rmax, 2));
      const float mnew = fmaxf(mi[h2], rmax);
      const float corr = fexp(mi[h2] - mnew);
      mi[h2] = mnew;
      float rsum = 0.f;
#pragma unroll
      for (int j = 0; j < 8; ++j) {
        float p0 = fexp(sc[j][h2 * 2] - mnew);
        float p1 = fexp(sc[j][h2 * 2 + 1] - mnew);
        rsum += p0 + p1;
        sc[j][h2 * 2] = p0;
        sc[j][h2 * 2 + 1] = p1;
      }
      rsum += __shfl_xor_sync(0xffffffffu, rsum, 1);
      rsum += __shfl_xor_sync(0xffffffffu, rsum, 2);
      li[h2] = li[h2] * corr + rsum;
#pragma unroll
      for (int j = 0; j < 8; ++j) {
        O[j][h2 * 2] *= corr;
        O[j][h2 * 2 + 1] *= corr;
      }
    }

    // P -> A fragments (hi/lo)
    uint32_t pah[4][4], pal[4][4];
#pragma unroll
    for (int g = 0; g < 4; ++g) {
      split_pack(sc[2 * g][0], sc[2 * g][1], pah[g][0], pal[g][0]);
      split_pack(sc[2 * g][2], sc[2 * g][3], pah[g][1], pal[g][1]);
      split_pack(sc[2 * g + 1][0], sc[2 * g + 1][1], pah[g][2], pal[g][2]);
      split_pack(sc[2 * g + 1][2], sc[2 * g + 1][3], pah[g][3], pal[g][3]);
    }

    // PV: O += P * V  (V B-frags via ldmatrix.trans on [key][dh] tiles)
#pragma unroll
    for (int g = 0; g < 4; ++g) {
#pragma unroll
      for (int n4 = 0; n4 < 4; ++n4) {
        uint32_t addr = kb + 2 * ATILE + (g * 16 + (lane & 15)) * 144 +
                        (n4 * 16 + ((lane >> 4) << 3)) * 2;
        uint32_t vfh[4], vfl[4];
        LDSM4T(vfh, addr);
        LDSM4T(vfl, addr + ATILE);
        MMA16816(O[n4 * 2], pah[g], vfh[0], vfh[1]);
        MMA16816(O[n4 * 2], pal[g], vfh[0], vfh[1]);
        MMA16816(O[n4 * 2], pah[g], vfl[0], vfl[1]);
        MMA16816(O[n4 * 2 + 1], pah[g], vfh[2], vfh[3]);
        MMA16816(O[n4 * 2 + 1], pal[g], vfh[2], vfh[3]);
        MMA16816(O[n4 * 2 + 1], pah[g], vfl[2], vfl[3]);
      }
    }
    __syncthreads();  // before next prefetch overwrites this buffer
  }

  // Epilogue: normalize, write ctx bf16 hi/lo in [B,S,D] layout
#pragma unroll
  for (int h2 = 0; h2 < 2; ++h2) {
    const float inv = 1.0f / li[h2];
    const int q = qm0 + wm + (lane >> 2) + h2 * 8;
    const size_t base = (size_t)(b * S_ + q) * D_ + h * 64 + (lane & 3) * 2;
#pragma unroll
    for (int j = 0; j < 8; ++j) {
      float v0 = O[j][h2 * 2] * inv;
      float v1 = O[j][h2 * 2 + 1] * inv;
      uint32_t hi2, lo2;
      split_pack(v0, v1, hi2, lo2);
      *(uint32_t*)&g_ctxhi[base + j * 8] = hi2;
      *(uint32_t*)&g_ctxlo[base + j * 8] = lo2;
    }
  }
}

// ---------------------------------------------------------------------------
extern "C" void kernel_launch(void* const* d_in, const int* in_sizes, int n_in,
                              void* d_out, int out_size) {
  const float* x     = (const float*)d_in[0];
  const int*   mask  = (const int*)d_in[1];
  const float* w_qkv = (const float*)d_in[2];
  const float* b_qkv = (const float*)d_in[3];
  const float* w_out = (const float*)d_in[4];
  const float* b_out = (const float*)d_in[5];
  float* out = (float*)d_out;

  void *pxh, *pxl, *pwth, *pwtl, *pwoh, *pwol, *pch, *pcl;
  cudaGetSymbolAddress(&pxh, g_xhi);
  cudaGetSymbolAddress(&pxl, g_xlo);
  cudaGetSymbolAddress(&pwth, g_wthi);
  cudaGetSymbolAddress(&pwtl, g_wtlo);
  cudaGetSymbolAddress(&pwoh, g_wothi);
  cudaGetSymbolAddress(&pwol, g_wotlo);
  cudaGetSymbolAddress(&pch, g_ctxhi);
  cudaGetSymbolAddress(&pcl, g_ctxlo);

  cudaFuncSetAttribute(mma_gemm,
                       cudaFuncAttributeMaxDynamicSharedMemorySize, GEMM_SMEM);
  cudaFuncSetAttribute(attn_mma,
                       cudaFuncAttributeMaxDynamicSharedMemorySize, ATTN_SMEM);

  // Split/convert inputs
  convert_split<<<(M_ * D_ / 4 + 255) / 256, 256>>>(
      x, M_ * D_ / 4, (__nv_bfloat16*)pxh, (__nv_bfloat16*)pxl);
  transpose_convert<<<dim3(N3D / 32, D_ / 32), dim3(32, 8)>>>(
      w_qkv, D_, N3D, (__nv_bfloat16*)pwth, (__nv_bfloat16*)pwtl);
  transpose_convert<<<dim3(D_ / 32, D_ / 32), dim3(32, 8)>>>(
      w_out, D_, D_, (__nv_bfloat16*)pwoh, (__nv_bfloat16*)pwol);

  // QKV projection -> head-major bf16 hi/lo q/k/v
  mma_gemm<<<dim3(N3D / 128, M_ / 128), 256, GEMM_SMEM>>>(
      (const __nv_bfloat16*)pxh, (const __nv_bfloat16*)pxl,
      (const __nv_bfloat16*)pwth, (const __nv_bfloat16*)pwtl, b_qkv, D_, 0,
      nullptr);

  // Tensor-core attention
  attn_mma<<<dim3(S_ / 64, B_ * H_), 128, ATTN_SMEM>>>(mask);

  // Output projection
  mma_gemm<<<dim3(D_ / 128, M_ / 128), 256, GEMM_SMEM>>>(
      (const __nv_bfloat16*)pch, (const __nv_bfloat16*)pcl,
      (const __nv_bfloat16*)pwoh, (const __nv_bfloat16*)pwol, b_out, D_, 1,
      out);
}

// round 13
// speedup vs baseline: 1.9282x; 1.0757x over previous
#include <cuda_runtime.h>
#include <cuda_bf16.h>
#include <cstdint>

// Problem constants
#define B_ 4
#define S_ 2048
#define D_ 1024
#define H_ 16
#define DH_ 64
#define N3D 3072           // 3*D
#define M_ (B_ * S_)       // 8192 rows

// ---------------------------------------------------------------------------
// Device scratch (allocation-free rule)
// ---------------------------------------------------------------------------
__device__ __align__(256) __nv_bfloat16 g_xhi[M_ * D_];
__device__ __align__(256) __nv_bfloat16 g_xlo[M_ * D_];
__device__ __align__(256) __nv_bfloat16 g_wthi[N3D * D_];   // W_qkv^T [n][k]
__device__ __align__(256) __nv_bfloat16 g_wtlo[N3D * D_];
__device__ __align__(256) __nv_bfloat16 g_wothi[D_ * D_];   // W_out^T [n][k]
__device__ __align__(256) __nv_bfloat16 g_wotlo[D_ * D_];
// head-major [bh][s][dh] bf16 hi/lo
__device__ __align__(256) __nv_bfloat16 g_qhi[B_ * H_ * S_ * DH_];
__device__ __align__(256) __nv_bfloat16 g_qlo[B_ * H_ * S_ * DH_];
__device__ __align__(256) __nv_bfloat16 g_khi[B_ * H_ * S_ * DH_];
__device__ __align__(256) __nv_bfloat16 g_klo[B_ * H_ * S_ * DH_];
__device__ __align__(256) __nv_bfloat16 g_vhi[B_ * H_ * S_ * DH_];
__device__ __align__(256) __nv_bfloat16 g_vlo[B_ * H_ * S_ * DH_];
__device__ __align__(256) __nv_bfloat16 g_ctxhi[M_ * D_];   // [b*S+s][d]
__device__ __align__(256) __nv_bfloat16 g_ctxlo[M_ * D_];

// ---------------------------------------------------------------------------
// PTX helpers (sm_80+ standard instructions only)
// ---------------------------------------------------------------------------
__device__ __forceinline__ uint32_t smem_to_u32(const void* p) {
  uint32_t a;
  asm("{ .reg .u64 t; cvta.to.shared.u64 t, %1; cvt.u32.u64 %0, t; }"
      : "=r"(a) : "l"(p));
  return a;
}

#define CP_ASYNC16(dst, src)                                              \
  asm volatile("cp.async.cg.shared.global [%0], [%1], 16;" ::"r"(dst),    \
               "l"(src) : "memory")
#define CP_COMMIT() asm volatile("cp.async.commit_group;" ::: "memory")
#define CP_WAIT1() asm volatile("cp.async.wait_group 1;" ::: "memory")
#define CP_WAIT0() asm volatile("cp.async.wait_group 0;" ::: "memory")

#define LDSM4(r, addr)                                                     \
  asm volatile(                                                            \
      "ldmatrix.sync.aligned.m8n8.x4.shared.b16 {%0,%1,%2,%3}, [%4];"      \
      : "=r"((r)[0]), "=r"((r)[1]), "=r"((r)[2]), "=r"((r)[3])             \
      : "r"(addr))

#define LDSM4T(r, addr)                                                    \
  asm volatile(                                                            \
      "ldmatrix.sync.aligned.m8n8.x4.trans.shared.b16 {%0,%1,%2,%3}, [%4];"\
      : "=r"((r)[0]), "=r"((r)[1]), "=r"((r)[2]), "=r"((r)[3])             \
      : "r"(addr))

#define MMA16816(c, a, b0, b1)                                              \
  asm volatile(                                                             \
      "mma.sync.aligned.m16n8k16.row.col.f32.bf16.bf16.f32 "                \
      "{%0,%1,%2,%3}, {%4,%5,%6,%7}, {%8,%9}, {%0,%1,%2,%3};"               \
      : "+f"((c)[0]), "+f"((c)[1]), "+f"((c)[2]), "+f"((c)[3])              \
      : "r"((a)[0]), "r"((a)[1]), "r"((a)[2]), "r"((a)[3]), "r"(b0),        \
        "r"(b1))

// FFMA-only exp (no MUFU): magic-constant round + degree-5 poly for 2^f.
__device__ __forceinline__ float fexp(float x) {
  float z = fmaf(x, 1.4426950408889634f, 12582912.0f);  // n in low mantissa
  float n = z - 12582912.0f;                            // round(x*log2e)
  float f = fmaf(x, 1.4426950408889634f, -n);           // [-0.5, 0.5]
  float p = 1.33335581e-3f;
  p = fmaf(p, f, 9.61812911e-3f);
  p = fmaf(p, f, 5.55041087e-2f);
  p = fmaf(p, f, 2.40226507e-1f);
  p = fmaf(p, f, 6.93147181e-1f);
  p = fmaf(p, f, 1.0f);
  int ni = __float_as_int(z) - 0x4B400000;  // = (int)n
  ni = max(ni, -126);
  return p * __int_as_float((ni + 127) << 23);
}

// Split float pair into bf16x2 hi + bf16x2 lo (residual) regs.
__device__ __forceinline__ void split_pack(float a, float b, uint32_t& hi2,
                                           uint32_t& lo2) {
  __nv_bfloat162 hh, ll;
  hh.x = __float2bfloat16(a);
  hh.y = __float2bfloat16(b);
  ll.x = __float2bfloat16(a - __bfloat162float(hh.x));
  ll.y = __float2bfloat16(b - __bfloat162float(hh.y));
  hi2 = *(uint32_t*)&hh;
  lo2 = *(uint32_t*)&ll;
}

// ---------------------------------------------------------------------------
// Converters
// ---------------------------------------------------------------------------
__global__ void convert_split(const float* __restrict__ X, int n4,
                              __nv_bfloat16* __restrict__ hi,
                              __nv_bfloat16* __restrict__ lo) {
  int i = blockIdx.x * blockDim.x + threadIdx.x;
  if (i >= n4) return;
  float4 v = ((const float4*)X)[i];
  __nv_bfloat162 ha, hb, la, lb;
  ha.x = __float2bfloat16(v.x);
  ha.y = __float2bfloat16(v.y);
  hb.x = __float2bfloat16(v.z);
  hb.y = __float2bfloat16(v.w);
  la.x = __float2bfloat16(v.x - __bfloat162float(ha.x));
  la.y = __float2bfloat16(v.y - __bfloat162float(ha.y));
  lb.x = __float2bfloat16(v.z - __bfloat162float(hb.x));
  lb.y = __float2bfloat16(v.w - __bfloat162float(hb.y));
  ((__nv_bfloat162*)hi)[2 * i] = ha;
  ((__nv_bfloat162*)hi)[2 * i + 1] = hb;
  ((__nv_bfloat162*)lo)[2 * i] = la;
  ((__nv_bfloat162*)lo)[2 * i + 1] = lb;
}

__global__ void transpose_convert(const float* __restrict__ W, int Kd, int Nd,
                                  __nv_bfloat16* __restrict__ WT_hi,
                                  __nv_bfloat16* __restrict__ WT_lo) {
  __shared__ float t[32][33];
  int n0 = blockIdx.x * 32, k0 = blockIdx.y * 32;
  int tx = threadIdx.x;
  for (int r = threadIdx.y; r < 32; r += 8)
    t[r][tx] = W[(size_t)(k0 + r) * Nd + n0 + tx];
  __syncthreads();
  for (int r = threadIdx.y; r < 32; r += 8) {
    float v = t[tx][r];  // = W[k0+tx][n0+r]
    __nv_bfloat16 h = __float2bfloat16(v);
    size_t o = (size_t)(n0 + r) * Kd + k0 + tx;
    WT_hi[o] = h;
    WT_lo[o] = __float2bfloat16(v - __bfloat162float(h));
  }
}

// ---------------------------------------------------------------------------
// bf16x3 GEMM via mma.sync: C[M,N] = A[M,K] @ B^T[N,K] + bias
// CTA tile 128x64, 8 warps of 32x32, BK=64, double-buffered cp.async,
// 2 CTAs/SM (regs<=128, smem 108KB). Row pad 144 B (conflict-free ldmatrix).
//   mode 0: split-scatter into head-major bf16 hi/lo q/k/v globals
//   mode 1: row-major fp32 out
// ---------------------------------------------------------------------------
#define A_TILE 18432            // 128 rows * 144 B
#define B_TILE 9216             // 64 rows * 144 B
#define S_AH 0
#define S_AL A_TILE
#define S_BH (2 * A_TILE)
#define S_BL (2 * A_TILE + B_TILE)
#define STAGE_B (2 * A_TILE + 2 * B_TILE)   // 55296
#define GEMM_SMEM (2 * STAGE_B)             // 110592

__device__ __forceinline__ void stage_copy(uint32_t sb,
                                           const __nv_bfloat16* gAh,
                                           const __nv_bfloat16* gAl,
                                           const __nv_bfloat16* gBh,
                                           const __nv_bfloat16* gBl,
                                           int Kdim, int kt, int tid) {
  const int koff = kt * 64;
  // A hi/lo: 128 rows x 8 chunks of 16B each
#pragma unroll
  for (int i = 0; i < 4; ++i) {
    int id = tid + 256 * i;
    int row = id >> 3, c = id & 7;
    size_t g = (size_t)row * Kdim + koff + c * 8;
    CP_ASYNC16(sb + S_AH + row * 144 + c * 16, gAh + g);
  }
#pragma unroll
  for (int i = 0; i < 4; ++i) {
    int id = tid + 256 * i;
    int row = id >> 3, c = id & 7;
    size_t g = (size_t)row * Kdim + koff + c * 8;
    CP_ASYNC16(sb + S_AL + row * 144 + c * 16, gAl + g);
  }
  // B hi/lo: 64 rows x 8 chunks
#pragma unroll
  for (int i = 0; i < 2; ++i) {
    int id = tid + 256 * i;
    int row = id >> 3, c = id & 7;
    size_t g = (size_t)row * Kdim + koff + c * 8;
    CP_ASYNC16(sb + S_BH + row * 144 + c * 16, gBh + g);
  }
#pragma unroll
  for (int i = 0; i < 2; ++i) {
    int id = tid + 256 * i;
    int row = id >> 3, c = id & 7;
    size_t g = (size_t)row * Kdim + koff + c * 8;
    CP_ASYNC16(sb + S_BL + row * 144 + c * 16, gBl + g);
  }
}

__global__ __launch_bounds__(256, 2) void mma_gemm(
    const __nv_bfloat16* __restrict__ Ah, const __nv_bfloat16* __restrict__ Al,
    const __nv_bfloat16* __restrict__ Bh, const __nv_bfloat16* __restrict__ Bl,
    const float* __restrict__ bias, int Kdim, int mode,
    float* __restrict__ outp) {
  extern __shared__ __align__(1024) char smem[];
  const uint32_t sm0 = smem_to_u32(smem);
  const int tid = threadIdx.x;
  const int lane = tid & 31;
  const int wid = tid >> 5;
  const int bn0 = blockIdx.x * 64;
  const int bm0 = blockIdx.y * 128;
  const int wm = (wid >> 1) * 32;   // warp m offset (0,32,64,96)
  const int wn = (wid & 1) * 32;    // warp n offset (0,32)

  const __nv_bfloat16* gAh = Ah + (size_t)bm0 * Kdim;
  const __nv_bfloat16* gAl = Al + (size_t)bm0 * Kdim;
  const __nv_bfloat16* gBh = Bh + (size_t)bn0 * Kdim;
  const __nv_bfloat16* gBl = Bl + (size_t)bn0 * Kdim;

  float acc[2][4][4];
#pragma unroll
  for (int f = 0; f < 2; ++f)
#pragma unroll
    for (int j = 0; j < 4; ++j)
#pragma unroll
      for (int r = 0; r < 4; ++r) acc[f][j][r] = 0.f;

  const int nkt = Kdim >> 6;
  stage_copy(sm0, gAh, gAl, gBh, gBl, Kdim, 0, tid);
  CP_COMMIT();
  stage_copy(sm0 + STAGE_B, gAh, gAl, gBh, gBl, Kdim, 1, tid);
  CP_COMMIT();

  const uint32_t lrow = lane & 15;
  const uint32_t lsel = (lane >> 4) * 16;

  for (int kt = 0; kt < nkt; ++kt) {
    if (kt == nkt - 1) CP_WAIT0(); else CP_WAIT1();
    __syncthreads();
    const uint32_t sb = sm0 + (kt & 1) * STAGE_B;
    const uint32_t aBaseH = sb + S_AH + (wm + lrow) * 144 + lsel;
    const uint32_t aBaseL = sb + S_AL + (wm + lrow) * 144 + lsel;
    const uint32_t bBaseH = sb + S_BH + (wn + lrow) * 144 + lsel;
    const uint32_t bBaseL = sb + S_BL + (wn + lrow) * 144 + lsel;

#pragma unroll
    for (int s = 0; s < 4; ++s) {
      const uint32_t ko = s * 32;
      uint32_t ah[2][4], al[2][4], bh[2][4], bl[2][4];
#pragma unroll
      for (int f = 0; f < 2; ++f) {
        LDSM4(ah[f], aBaseH + f * (16 * 144) + ko);
        LDSM4(al[f], aBaseL + f * (16 * 144) + ko);
      }
#pragma unroll
      for (int g = 0; g < 2; ++g) {
        LDSM4(bh[g], bBaseH + g * (16 * 144) + ko);
        LDSM4(bl[g], bBaseL + g * (16 * 144) + ko);
      }
#pragma unroll
      for (int f = 0; f < 2; ++f) {
#pragma unroll
        for (int j = 0; j < 4; ++j) {
          const int g = j >> 1, hb = j & 1;
          MMA16816(acc[f][j], ah[f], bh[g][hb], bh[g][hb + 2]);
          MMA16816(acc[f][j], ah[f], bl[g][hb], bl[g][hb + 2]);
          MMA16816(acc[f][j], al[f], bh[g][hb], bh[g][hb + 2]);
        }
      }
    }
    __syncthreads();
    if (kt + 2 < nkt) {
      stage_copy(sb, gAh, gAl, gBh, gBl, Kdim, kt + 2, tid);
      CP_COMMIT();
    }
  }

  // Epilogue
  const int rbase = bm0 + wm + (lane >> 2);
  const int cbase = bn0 + wn + (lane & 3) * 2;
#pragma unroll
  for (int f = 0; f < 2; ++f) {
#pragma unroll
    for (int j = 0; j < 4; ++j) {
      const int col = cbase + j * 8;
      const float bx = __ldg(&bias[col]);
      const float by = __ldg(&bias[col + 1]);
      const int m0 = rbase + f * 16;
      if (mode == 0) {
        const int which = col >> 10;
        const int h = (col >> 6) & 15;
        const int dh = col & 63;
        __nv_bfloat16 *dsth, *dstl;
        if (which == 0) { dsth = g_qhi; dstl = g_qlo; }
        else if (which == 1) { dsth = g_khi; dstl = g_klo; }
        else { dsth = g_vhi; dstl = g_vlo; }
#pragma unroll
        for (int half = 0; half < 2; ++half) {
          const int m = m0 + half * 8;
          const int b = m >> 11, s = m & 2047;
          float v0 = acc[f][j][half * 2] + bx;
          float v1 = acc[f][j][half * 2 + 1] + by;
          uint32_t hi2, lo2;
          split_pack(v0, v1, hi2, lo2);
          size_t o = (size_t)(((b << 4) + h) * 2048 + s) * 64 + dh;
          *(uint32_t*)&dsth[o] = hi2;
          *(uint32_t*)&dstl[o] = lo2;
        }
      } else {
#pragma unroll
        for (int half = 0; half < 2; ++half) {
          const int m = m0 + half * 8;
          float2 v2 = make_float2(acc[f][j][half * 2] + bx,
                                  acc[f][j][half * 2 + 1] + by);
          *(float2*)&outp[(size_t)m * 1024 + col] = v2;
        }
      }
    }
  }
}

// ---------------------------------------------------------------------------
// Tensor-core flash attention, bf16x3, fp32 accum, online softmax.
// Grid (S/64, B*H), 128 threads (4 warps x 16 q-rows). K/V double-buffered.
// Q staged through KV buffer 0 (frags persist in regs) -> smem 73.7KB
// -> 3 CTAs/SM.
// ---------------------------------------------------------------------------
#define ATILE 9216                 // 64*144
#define AKV (4 * ATILE)            // one K/V buffer (Khi,Klo,Vhi,Vlo)
#define ATTN_SMEM (2 * AKV)        // 73728

__device__ __forceinline__ void kv_stage(uint32_t db, const __nv_bfloat16* Kh,
                                         const __nv_bfloat16* Kl,
                                         const __nv_bfloat16* Vh,
                                         const __nv_bfloat16* Vl, int kn0,
                                         int tid) {
  const __nv_bfloat16* src[4] = {Kh, Kl, Vh, Vl};
#pragma unroll
  for (int t = 0; t < 4; ++t) {
    const __nv_bfloat16* g = src[t] + (size_t)kn0 * 64;
    uint32_t tb = db + t * ATILE;
#pragma unroll
    for (int i = 0; i < 4; ++i) {
      int idx = tid + 128 * i;   // 512 chunks: 64 rows x 8 x 16B
      int row = idx >> 3, c = idx & 7;
      CP_ASYNC16(tb + row * 144 + c * 16, g + row * 64 + c * 8);
    }
  }
}

__global__ __launch_bounds__(128, 3) void attn_mma(const int* __restrict__ mask) {
  extern __shared__ __align__(1024) char smem[];
  const uint32_t s0 = smem_to_u32(smem);
  const int tid = threadIdx.x;
  const int lane = tid & 31;
  const int wid = tid >> 5;
  const int qb = blockIdx.x;
  const int bh = blockIdx.y;
  const int b = bh >> 4;
  const int h = bh & 15;
  const int qm0 = qb * 64;
  const int wm = wid * 16;

  const size_t hb_off = (size_t)bh * (S_ * DH_);
  const __nv_bfloat16* Qh = g_qhi + hb_off + (size_t)qm0 * DH_;
  const __nv_bfloat16* Ql = g_qlo + hb_off + (size_t)qm0 * DH_;
  const __nv_bfloat16* Kh = g_khi + hb_off;
  const __nv_bfloat16* Kl = g_klo + hb_off;
  const __nv_bfloat16* Vh = g_vhi + hb_off;
  const __nv_bfloat16* Vl = g_vlo + hb_off;

  // Stage Q (hi/lo) through KV buffer 0, extract fragments, then release.
#pragma unroll
  for (int i = 0; i < 4; ++i) {
    int idx = tid + 128 * i;   // 512 chunks
    int row = idx >> 3, c = idx & 7;
    *(uint4*)(smem + row * 144 + c * 16) = *(const uint4*)(Qh + row * 64 + c * 8);
    *(uint4*)(smem + ATILE + row * 144 + c * 16) =
        *(const uint4*)(Ql + row * 64 + c * 8);
  }
  __syncthreads();

  uint32_t qh[4][4], ql[4][4];
  {
    uint32_t base = s0 + (wm + (lane & 15)) * 144 + ((lane >> 4) << 4);
#pragma unroll
    for (int s = 0; s < 4; ++s) {
      LDSM4(qh[s], base + s * 32);
      LDSM4(ql[s], base + ATILE + s * 32);
    }
  }
  __syncthreads();  // all warps done reading Q before KV overwrites buf0

  kv_stage(s0, Kh, Kl, Vh, Vl, 0, tid);
  CP_COMMIT();

  float O[8][4];
#pragma unroll
  for (int j = 0; j < 8; ++j)
#pragma unroll
    for (int r = 0; r < 4; ++r) O[j][r] = 0.f;
  float mi[2] = {-1001.f, -1001.f};
  float li[2] = {0.f, 0.f};

  for (int kt = 0; kt < 32; ++kt) {
    if (kt + 1 < 32) {
      kv_stage(s0 + ((kt + 1) & 1) * AKV, Kh, Kl, Vh, Vl, (kt + 1) * 64, tid);
      CP_COMMIT();
      CP_WAIT1();
    } else {
      CP_WAIT0();
    }
    __syncthreads();
    const uint32_t kb = s0 + (kt & 1) * AKV;

    // scores: 64x64 per CTA (16x64 per warp)
    float sc[8][4];
#pragma unroll
    for (int j = 0; j < 8; ++j)
#pragma unroll
      for (int r = 0; r < 4; ++r) sc[j][r] = 0.f;

#pragma unroll
    for (int s = 0; s < 4; ++s) {
      uint32_t kfh[4][4], kfl[4][4];
#pragma unroll
      for (int g = 0; g < 4; ++g) {
        uint32_t a = kb + (g * 16 + (lane & 15)) * 144 + ((lane >> 4) << 4) +
                     s * 32;
        LDSM4(kfh[g], a);
        LDSM4(kfl[g], a + ATILE);
      }
#pragma unroll
      for (int g = 0; g < 4; ++g) {
#pragma unroll
        for (int hb2 = 0; hb2 < 2; ++hb2) {
          const int j = g * 2 + hb2;
          MMA16816(sc[j], qh[s], kfh[g][hb2], kfh[g][hb2 + 2]);
          MMA16816(sc[j], qh[s], kfl[g][hb2], kfl[g][hb2 + 2]);
          MMA16816(sc[j], ql[s], kfh[g][hb2], kfh[g][hb2 + 2]);
        }
      }
    }

    // softmax (mask + scale + online update)
    const int kn0 = kt * 64;
#pragma unroll
    for (int h2 = 0; h2 < 2; ++h2) {
      const int qrow = qm0 + wm + (lane >> 2) + h2 * 8;
      const int* mrow =
          mask + (size_t)b * S_ * S_ + (size_t)qrow * S_ + kn0 + (lane & 3) * 2;
      float rmax = -1e30f;
#pragma unroll
      for (int j = 0; j < 8; ++j) {
        int2 mv = __ldg((const int2*)(mrow + j * 8));
        float x0 = mv.x ? sc[j][h2 * 2] * 0.125f : -1000.f;
        float x1 = mv.y ? sc[j][h2 * 2 + 1] * 0.125f : -1000.f;
        sc[j][h2 * 2] = x0;
        sc[j][h2 * 2 + 1] = x1;
        rmax = fmaxf(rmax, fmaxf(x0, x1));
      }
      rmax = fmaxf(rmax, __shfl_xor_sync(0xffffffffu, rmax, 1));
      rmax = fmaxf(rmax, __shfl_xor_sync(0xffffffffu, rmax, 2));
      const float mnew = fmaxf(mi[h2], rmax);
      const float corr = fexp(mi[h2] - mnew);
      mi[h2] = mnew;
      float rsum = 0.f;
#pragma unroll
      for (int j = 0; j < 8; ++j) {
        float p0 = fexp(sc[j][h2 * 2] - mnew);
        float p1 = fexp(sc[j][h2 * 2 + 1] - mnew);
        rsum += p0 + p1;
        sc[j][h2 * 2] = p0;
        sc[j][h2 * 2 + 1] = p1;
      }
      rsum += __shfl_xor_sync(0xffffffffu, rsum, 1);
      rsum += __shfl_xor_sync(0xffffffffu, rsum, 2);
      li[h2] = li[h2] * corr + rsum;
#pragma unroll
      for (int j = 0; j < 8; ++j) {
        O[j][h2 * 2] *= corr;
        O[j][h2 * 2 + 1] *= corr;
      }
    }

    // P -> A fragments (hi/lo)
    uint32_t pah[4][4], pal[4][4];
#pragma unroll
    for (int g = 0; g < 4; ++g) {
      split_pack(sc[2 * g][0], sc[2 * g][1], pah[g][0], pal[g][0]);
      split_pack(sc[2 * g][2], sc[2 * g][3], pah[g][1], pal[g][1]);
      split_pack(sc[2 * g + 1][0], sc[2 * g + 1][1], pah[g][2], pal[g][2]);
      split_pack(sc[2 * g + 1][2], sc[2 * g + 1][3], pah[g][3], pal[g][3]);
    }

    // PV: O += P * V  (V B-frags via ldmatrix.trans on [key][dh] tiles)
#pragma unroll
    for (int g = 0; g < 4; ++g) {
#pragma unroll
      for (int n4 = 0; n4 < 4; ++n4) {
        uint32_t addr = kb + 2 * ATILE + (g * 16 + (lane & 15)) * 144 +
                        (n4 * 16 + ((lane >> 4) << 3)) * 2;
        uint32_t vfh[4], vfl[4];
        LDSM4T(vfh, addr);
        LDSM4T(vfl, addr + ATILE);
        MMA16816(O[n4 * 2], pah[g], vfh[0], vfh[1]);
        MMA16816(O[n4 * 2], pal[g], vfh[0], vfh[1]);
        MMA16816(O[n4 * 2], pah[g], vfl[0], vfl[1]);
        MMA16816(O[n4 * 2 + 1], pah[g], vfh[2], vfh[3]);
        MMA16816(O[n4 * 2 + 1], pal[g], vfh[2], vfh[3]);
        MMA16816(O[n4 * 2 + 1], pah[g], vfl[2], vfl[3]);
      }
    }
    __syncthreads();  // before next prefetch overwrites this buffer
  }

  // Epilogue: normalize, write ctx bf16 hi/lo in [B,S,D] layout
#pragma unroll
  for (int h2 = 0; h2 < 2; ++h2) {
    const float inv = 1.0f / li[h2];
    const int q = qm0 + wm + (lane >> 2) + h2 * 8;
    const size_t base = (size_t)(b * S_ + q) * D_ + h * 64 + (lane & 3) * 2;
#pragma unroll
    for (int j = 0; j < 8; ++j) {
      float v0 = O[j][h2 * 2] * inv;
      float v1 = O[j][h2 * 2 + 1] * inv;
      uint32_t hi2, lo2;
      split_pack(v0, v1, hi2, lo2);
      *(uint32_t*)&g_ctxhi[base + j * 8] = hi2;
      *(uint32_t*)&g_ctxlo[base + j * 8] = lo2;
    }
  }
}

// ---------------------------------------------------------------------------
extern "C" void kernel_launch(void* const* d_in, const int* in_sizes, int n_in,
                              void* d_out, int out_size) {
  const float* x     = (const float*)d_in[0];
  const int*   mask  = (const int*)d_in[1];
  const float* w_qkv = (const float*)d_in[2];
  const float* b_qkv = (const float*)d_in[3];
  const float* w_out = (const float*)d_in[4];
  const float* b_out = (const float*)d_in[5];
  float* out = (float*)d_out;

  void *pxh, *pxl, *pwth, *pwtl, *pwoh, *pwol, *pch, *pcl;
  cudaGetSymbolAddress(&pxh, g_xhi);
  cudaGetSymbolAddress(&pxl, g_xlo);
  cudaGetSymbolAddress(&pwth, g_wthi);
  cudaGetSymbolAddress(&pwtl, g_wtlo);
  cudaGetSymbolAddress(&pwoh, g_wothi);
  cudaGetSymbolAddress(&pwol, g_wotlo);
  cudaGetSymbolAddress(&pch, g_ctxhi);
  cudaGetSymbolAddress(&pcl, g_ctxlo);

  cudaFuncSetAttribute(mma_gemm,
                       cudaFuncAttributeMaxDynamicSharedMemorySize, GEMM_SMEM);
  cudaFuncSetAttribute(attn_mma,
                       cudaFuncAttributeMaxDynamicSharedMemorySize, ATTN_SMEM);

  // Split/convert inputs
  convert_split<<<(M_ * D_ / 4 + 255) / 256, 256>>>(
      x, M_ * D_ / 4, (__nv_bfloat16*)pxh, (__nv_bfloat16*)pxl);
  transpose_convert<<<dim3(N3D / 32, D_ / 32), dim3(32, 8)>>>(
      w_qkv, D_, N3D, (__nv_bfloat16*)pwth, (__nv_bfloat16*)pwtl);
  transpose_convert<<<dim3(D_ / 32, D_ / 32), dim3(32, 8)>>>(
      w_out, D_, D_, (__nv_bfloat16*)pwoh, (__nv_bfloat16*)pwol);

  // QKV projection -> head-major bf16 hi/lo q/k/v
  mma_gemm<<<dim3(N3D / 64, M_ / 128), 256, GEMM_SMEM>>>(
      (const __nv_bfloat16*)pxh, (const __nv_bfloat16*)pxl,
      (const __nv_bfloat16*)pwth, (const __nv_bfloat16*)pwtl, b_qkv, D_, 0,
      nullptr);

  // Tensor-core attention
  attn_mma<<<dim3(S_ / 64, B_ * H_), 128, ATTN_SMEM>>>(mask);

  // Output projection
  mma_gemm<<<dim3(D_ / 64, M_ / 128), 256, GEMM_SMEM>>>(
      (const __nv_bfloat16*)pch, (const __nv_bfloat16*)pcl,
      (const __nv_bfloat16*)pwoh, (const __nv_bfloat16*)pwol, b_out, D_, 1,
      out);
}